// round 13
// baseline (speedup 1.0000x reference)
#include <cuda_runtime.h>
#include <cstdint>
#include <math.h>

#define U 256
#define INWID 128
#define BATCH 128
#define TLEN 1024
#define OUTD 400

// d_out layout: output [B*400] | d_t [B*256] | gru1_h [B*256] | gru2_h [B*256]
#define OUT_OFF 0
#define DT_OFF  (BATCH*OUTD)
#define G1_OFF  (DT_OFF + BATCH*U)
#define G2_OFF  (G1_OFF + BATCH*U)

// -------- scratch (no allocations allowed) --------
__device__ __align__(16) float g_W1tp[256 * 264];   // tf32, transposed, padded rows
__device__ __align__(16) float g_query[BATCH * U];
__device__ __align__(16) float g_scores[BATCH * TLEN];
__device__ __align__(16) float g_ctxpart[BATCH * 4 * U];
__device__ __align__(16) float g_ghA[BATCH * 3 * U];
__device__ __align__(16) float g_gh1[BATCH * 3 * U];
__device__ __align__(16) float g_gh2[BATCH * 3 * U];
__device__ __align__(16) float g_cat[BATCH * 2 * U];
__device__ __align__(16) float g_x1[BATCH * U];
__device__ __align__(16) float g_x2[BATCH * U];
__device__ __align__(16) float g_bf[BATCH * U];

__device__ __forceinline__ float sigmoidf_(float x) {
    return 1.0f / (1.0f + __expf(-x));
}
__device__ __forceinline__ float tanh_fast(float x) {
    float y;
    asm("tanh.approx.f32 %0, %1;" : "=f"(y) : "f"(x));
    return y;
}
__device__ __forceinline__ uint32_t f32_to_tf32(float x) {
    uint32_t r;
    asm("cvt.rna.tf32.f32 %0, %1;" : "=r"(r) : "f"(x));
    return r;
}
__device__ __forceinline__ float tf32v(float x) {
    return __uint_as_float(f32_to_tf32(x));
}
__device__ __forceinline__ void mma_tf32(float c[4], const uint32_t a[4], const uint32_t b[2]) {
    asm volatile(
        "mma.sync.aligned.m16n8k8.row.col.f32.tf32.tf32.f32 "
        "{%0,%1,%2,%3}, {%4,%5,%6,%7}, {%8,%9}, {%0,%1,%2,%3};\n"
        : "+f"(c[0]), "+f"(c[1]), "+f"(c[2]), "+f"(c[3])
        : "r"(a[0]), "r"(a[1]), "r"(a[2]), "r"(a[3]), "r"(b[0]), "r"(b[1]));
}
__device__ __forceinline__ uint32_t smem_u32(const void* p) {
    uint32_t a;
    asm("{ .reg .u64 t; cvta.to.shared.u64 t, %1; cvt.u32.u64 %0, t; }" : "=r"(a) : "l"(p));
    return a;
}
__device__ __forceinline__ void cp_async16(uint32_t dst, const void* src) {
    asm volatile("cp.async.ca.shared.global [%0], [%1], 16;\n" :: "r"(dst), "l"(src));
}
__device__ __forceinline__ void cp_async16_p(uint32_t dst, const void* src, bool pred) {
    int sz = pred ? 16 : 0;
    asm volatile("cp.async.ca.shared.global [%0], [%1], 16, %2;\n"
                 :: "r"(dst), "l"(src), "r"(sz));
}
__device__ __forceinline__ void cp_commit() {
    asm volatile("cp.async.commit_group;\n");
}
__device__ __forceinline__ void cp_wait1() {
    asm volatile("cp.async.wait_group 1;\n" ::: "memory");
}
__device__ __forceinline__ void cp_wait0() {
    asm volatile("cp.async.wait_group 0;\n" ::: "memory");
}

// ================= prep: W1 [j][k] -> W1tp [k][j] (tf32, 264-stride) ========
__global__ void k_prepW1(const float* __restrict__ W1) {
    __shared__ float tile[32][33];
    int k0 = blockIdx.x * 32, j0 = blockIdx.y * 32;
    int tx = threadIdx.x, ty = threadIdx.y;  // 32 x 8
#pragma unroll
    for (int r = 0; r < 32; r += 8)
        tile[ty + r][tx] = W1[(j0 + ty + r) * U + k0 + tx];
    __syncthreads();
#pragma unroll
    for (int r = 0; r < 32; r += 8)
        g_W1tp[(size_t)(k0 + ty + r) * 264 + j0 + tx] = tf32v(tile[tx][ty + r]);
}

// ================= K2: scores via pipelined tf32 mma (unchanged) ============
__global__ void __launch_bounds__(256, 1)
k_scores3(const float* __restrict__ memory, const float* __restrict__ v) {
    extern __shared__ float dsm[];
    float* Abuf = dsm;                         // 2 * 4608 floats
    float* Bbuf = dsm + 2 * 128 * 36;          // 2 * 8448 floats
    __shared__ float sq[U], sv[U];
    __shared__ float spart[128][4];

    int b = blockIdx.x, t0 = blockIdx.y * 128;
    int tid = threadIdx.x, lane = tid & 31, w = tid >> 5;

    sq[tid] = g_query[b * U + tid];
    sv[tid] = v[tid];

    const float* Abase = memory + ((size_t)b * TLEN + t0) * U;

    int mbase = (w & 1) * 64;
    int nbase = (w >> 1) * 64;
    int r0 = lane >> 2, cA = lane & 3;
    int rB = lane & 3, cB = lane >> 2;

    float acc[4][8][4];
#pragma unroll
    for (int mt = 0; mt < 4; mt++)
#pragma unroll
        for (int nt = 0; nt < 8; nt++)
#pragma unroll
            for (int i = 0; i < 4; i++) acc[mt][nt][i] = 0.0f;

#pragma unroll
    for (int i = 0; i < 4; i++) {
        int u = tid + 256 * i;
        int row = u >> 3, c4 = (u & 7) * 4;
        cp_async16(smem_u32(Abuf + row * 36 + c4), Abase + (size_t)row * U + c4);
    }
#pragma unroll
    for (int i = 0; i < 8; i++) {
        int u = tid + 256 * i;
        int row = u >> 6, c4 = (u & 63) * 4;
        cp_async16(smem_u32(Bbuf + row * 264 + c4), g_W1tp + (size_t)row * 264 + c4);
    }
    cp_commit();

    for (int kc = 0; kc < 8; kc++) {
        int buf = kc & 1;
        if (kc < 7) {
            float* An = Abuf + (buf ^ 1) * 4608;
            float* Bn = Bbuf + (buf ^ 1) * 8448;
#pragma unroll
            for (int i = 0; i < 4; i++) {
                int u = tid + 256 * i;
                int row = u >> 3, c4 = (u & 7) * 4;
                cp_async16(smem_u32(An + row * 36 + c4),
                           Abase + (size_t)row * U + (kc + 1) * 32 + c4);
            }
#pragma unroll
            for (int i = 0; i < 8; i++) {
                int u = tid + 256 * i;
                int row = u >> 6, c4 = (u & 63) * 4;
                cp_async16(smem_u32(Bn + row * 264 + c4),
                           g_W1tp + (size_t)((kc + 1) * 32 + row) * 264 + c4);
            }
            cp_commit();
            cp_wait1();
        } else {
            cp_wait0();
        }
        __syncthreads();

        const float* Ac = Abuf + buf * 4608;
        const float* Bc = Bbuf + buf * 8448;
#pragma unroll
        for (int kk = 0; kk < 32; kk += 8) {
            uint32_t a[4][4];
#pragma unroll
            for (int mt = 0; mt < 4; mt++) {
                a[mt][0] = f32_to_tf32(Ac[(mbase + mt * 16 + r0) * 36 + kk + cA]);
                a[mt][1] = f32_to_tf32(Ac[(mbase + mt * 16 + r0 + 8) * 36 + kk + cA]);
                a[mt][2] = f32_to_tf32(Ac[(mbase + mt * 16 + r0) * 36 + kk + cA + 4]);
                a[mt][3] = f32_to_tf32(Ac[(mbase + mt * 16 + r0 + 8) * 36 + kk + cA + 4]);
            }
            uint32_t bb[8][2];
#pragma unroll
            for (int nt = 0; nt < 8; nt++) {
                int j = nbase + nt * 8 + cB;
                bb[nt][0] = __float_as_uint(Bc[(kk + rB) * 264 + j]);
                bb[nt][1] = __float_as_uint(Bc[(kk + rB + 4) * 264 + j]);
            }
#pragma unroll
            for (int mt = 0; mt < 4; mt++)
#pragma unroll
                for (int nt = 0; nt < 8; nt++)
                    mma_tf32(acc[mt][nt], a[mt], bb[nt]);
        }
        __syncthreads();
    }

    float part[8];
#pragma unroll
    for (int i = 0; i < 8; i++) part[i] = 0.0f;
    int q4 = lane & 3;
#pragma unroll
    for (int mt = 0; mt < 4; mt++) {
#pragma unroll
        for (int nt = 0; nt < 8; nt++) {
            int j0 = nbase + nt * 8 + 2 * q4;
            float q0 = sq[j0], q1 = sq[j0 + 1];
            float v0 = sv[j0], v1 = sv[j0 + 1];
            part[mt * 2 + 0] += v0 * tanh_fast(acc[mt][nt][0] + q0) + v1 * tanh_fast(acc[mt][nt][1] + q1);
            part[mt * 2 + 1] += v0 * tanh_fast(acc[mt][nt][2] + q0) + v1 * tanh_fast(acc[mt][nt][3] + q1);
        }
    }
#pragma unroll
    for (int i = 0; i < 8; i++) {
        part[i] += __shfl_xor_sync(0xffffffffu, part[i], 1);
        part[i] += __shfl_xor_sync(0xffffffffu, part[i], 2);
    }
    if ((lane & 3) == 0) {
#pragma unroll
        for (int mt = 0; mt < 4; mt++) {
            spart[mbase + mt * 16 + r0][w >> 1] = part[mt * 2 + 0];
            spart[mbase + mt * 16 + r0 + 8][w >> 1] = part[mt * 2 + 1];
        }
    }
    __syncthreads();
    if (tid < 128) {
        float s = spart[tid][0] + spart[tid][1] + spart[tid][2] + spart[tid][3];
        g_scores[b * TLEN + t0 + tid] = s;
    }
}

// ================= One-shot GEMM: C[32 x 64 tile] = A @ W^T + bias ==========
// Whole K extent staged in SMEM with one cp.async wave; no K-chunk chain.
template<int K>
__device__ __forceinline__ void gemm_1s_body(const float* __restrict__ A, int lda,
                                             const float* __restrict__ W,
                                             const float* __restrict__ bias,
                                             float* __restrict__ C, int ldc,
                                             int N, int n0, int m0, float* dsm) {
    constexpr int SK = K + 12;
    constexpr int KQ = K / 4;
    float* Ab = dsm;             // 32 x SK
    float* Wb = dsm + 32 * SK;   // 64 x SK
    int tid = threadIdx.x, lane = tid & 31, w = tid >> 5;

#pragma unroll
    for (int i = 0; i < 32 * KQ / 256; i++) {
        int u = tid + 256 * i;
        int row = u / KQ, c4 = (u % KQ) * 4;
        cp_async16(smem_u32(Ab + row * SK + c4), A + (size_t)(m0 + row) * lda + c4);
    }
#pragma unroll
    for (int i = 0; i < 64 * KQ / 256; i++) {
        int u = tid + 256 * i;
        int row = u / KQ, c4 = (u % KQ) * 4;
        int n = n0 + row;
        cp_async16_p(smem_u32(Wb + row * SK + c4),
                     W + (size_t)(n < N ? n : N - 1) * K + c4, n < N);
    }
    cp_commit();
    cp_wait0();
    __syncthreads();

    int mbase = (w & 1) * 16, nbase = (w >> 1) * 16;
    int r0 = lane >> 2, cA = lane & 3;
    int rW = lane >> 2, cW = lane & 3;

    float acc[2][4];
#pragma unroll
    for (int nt = 0; nt < 2; nt++)
#pragma unroll
        for (int i = 0; i < 4; i++) acc[nt][i] = 0.0f;

#pragma unroll
    for (int kk = 0; kk < K; kk += 8) {
        uint32_t a[4];
        a[0] = f32_to_tf32(Ab[(mbase + r0) * SK + kk + cA]);
        a[1] = f32_to_tf32(Ab[(mbase + r0 + 8) * SK + kk + cA]);
        a[2] = f32_to_tf32(Ab[(mbase + r0) * SK + kk + cA + 4]);
        a[3] = f32_to_tf32(Ab[(mbase + r0 + 8) * SK + kk + cA + 4]);
#pragma unroll
        for (int nt = 0; nt < 2; nt++) {
            uint32_t bb[2];
            int nl = nbase + nt * 8 + rW;
            bb[0] = f32_to_tf32(Wb[nl * SK + kk + cW]);
            bb[1] = f32_to_tf32(Wb[nl * SK + kk + cW + 4]);
            mma_tf32(acc[nt], a, bb);
        }
    }

    int q4 = lane & 3;
#pragma unroll
    for (int nt = 0; nt < 2; nt++) {
        int m = m0 + mbase + r0;
        int n = n0 + nbase + nt * 8 + 2 * q4;
        if (n < N) {
            float b0 = bias ? bias[n] : 0.0f;
            float b1 = bias ? bias[n + 1] : 0.0f;
            C[(size_t)m * ldc + n]           = acc[nt][0] + b0;
            C[(size_t)m * ldc + n + 1]       = acc[nt][1] + b1;
            C[(size_t)(m + 8) * ldc + n]     = acc[nt][2] + b0;
            C[(size_t)(m + 8) * ldc + n + 1] = acc[nt][3] + b1;
        }
    }
}

template<int K>
__global__ void __launch_bounds__(256)
k_gemm_1s(const float* __restrict__ A, int lda, const float* __restrict__ W,
          const float* __restrict__ bias, float* __restrict__ C, int ldc, int N) {
    extern __shared__ float dsm[];
    gemm_1s_body<K>(A, lda, W, bias, C, ldc, N, blockIdx.x * 64, blockIdx.y * 32, dsm);
}

struct GemmJob {
    const float* A; const float* W; const float* bias; float* C;
    int lda; int ldc; int N;
};
struct GemmJobs3 { GemmJob j[3]; };

template<int K>
__global__ void __launch_bounds__(256)
k_gemm_multi_1s(GemmJobs3 jobs) {
    extern __shared__ float dsm[];
    GemmJob jb = jobs.j[blockIdx.z];
    gemm_1s_body<K>(jb.A, jb.lda, jb.W, jb.bias, jb.C, jb.ldc, jb.N,
                    blockIdx.x * 64, blockIdx.y * 32, dsm);
}

// ================= One-shot fused gate-GEMM + GRU combine =================
// Tile: 32 m-rows x 32 gate-cols (x3 gates). Grid (U/32, BATCH/32).
template<int K>
__global__ void __launch_bounds__(256)
k_gru_1s(const float* __restrict__ A, int lda,
         const float* __restrict__ Wih, const float* __restrict__ bih,
         const float* __restrict__ gh, const float* __restrict__ h0,
         float* __restrict__ hA, int sHA, float* __restrict__ hB,
         float* __restrict__ xout) {
    extern __shared__ float dsm[];
    constexpr int SK = K + 12;
    constexpr int KQ = K / 4;
    float* Ab = dsm;             // 32 x SK
    float* Wb = dsm + 32 * SK;   // 96 x SK
    int tid = threadIdx.x, lane = tid & 31, w = tid >> 5;
    int n0 = blockIdx.x * 32, m0 = blockIdx.y * 32;

#pragma unroll
    for (int i = 0; i < 32 * KQ / 256; i++) {
        int u = tid + 256 * i;
        int row = u / KQ, c4 = (u % KQ) * 4;
        cp_async16(smem_u32(Ab + row * SK + c4), A + (size_t)(m0 + row) * lda + c4);
    }
#pragma unroll
    for (int i = 0; i < 96 * KQ / 256; i++) {
        int u = tid + 256 * i;
        int row = u / KQ, c4 = (u % KQ) * 4;
        int wr = (row >> 5) * 256 + n0 + (row & 31);
        cp_async16(smem_u32(Wb + row * SK + c4), Wih + (size_t)wr * K + c4);
    }
    cp_commit();
    cp_wait0();
    __syncthreads();

    int mbase = (w & 1) * 16, nw8 = (w >> 1) * 8;
    int r0 = lane >> 2, cA = lane & 3;
    int rW = lane >> 2, cW = lane & 3;

    float acc[3][4];
#pragma unroll
    for (int g = 0; g < 3; g++)
#pragma unroll
        for (int i = 0; i < 4; i++) acc[g][i] = 0.0f;

#pragma unroll
    for (int kk = 0; kk < K; kk += 8) {
        uint32_t a[4];
        a[0] = f32_to_tf32(Ab[(mbase + r0) * SK + kk + cA]);
        a[1] = f32_to_tf32(Ab[(mbase + r0 + 8) * SK + kk + cA]);
        a[2] = f32_to_tf32(Ab[(mbase + r0) * SK + kk + cA + 4]);
        a[3] = f32_to_tf32(Ab[(mbase + r0 + 8) * SK + kk + cA + 4]);
#pragma unroll
        for (int g = 0; g < 3; g++) {
            uint32_t bb[2];
            int nl = g * 32 + nw8 + rW;
            bb[0] = f32_to_tf32(Wb[nl * SK + kk + cW]);
            bb[1] = f32_to_tf32(Wb[nl * SK + kk + cW + 4]);
            mma_tf32(acc[g], a, bb);
        }
    }

    int q4 = lane & 3;
#pragma unroll
    for (int half = 0; half < 2; half++) {
        int m = m0 + mbase + r0 + half * 8;
#pragma unroll
        for (int c = 0; c < 2; c++) {
            int nn = n0 + nw8 + 2 * q4 + c;
            int ai = half * 2 + c;
            float gir = acc[0][ai] + bih[nn];
            float giz = acc[1][ai] + bih[256 + nn];
            float gin = acc[2][ai] + bih[512 + nn];
            float ghr = gh[m * 768 + nn];
            float ghz = gh[m * 768 + 256 + nn];
            float ghn = gh[m * 768 + 512 + nn];
            float r = sigmoidf_(gir + ghr);
            float z = sigmoidf_(giz + ghz);
            float nv = tanhf(gin + r * ghn);
            float h = (1.0f - z) * nv + z * h0[m * 256 + nn];
            hA[(size_t)m * sHA + nn] = h;
            if (hB) hB[m * 256 + nn] = h;
            if (xout) xout[m * 256 + nn] = A[(size_t)m * lda + nn] + h;
        }
    }
}

// ============ context with fused softmax stats (grid B x 4) =================
__global__ void __launch_bounds__(256, 4)
k_context2(const float* __restrict__ memory) {
    int b = blockIdx.x, ch = blockIdx.y;
    int tid = threadIdx.x;
    int lane = tid & 31, warp = tid >> 5;

    __shared__ float red[8];
    __shared__ float sw[256];
    __shared__ float4 part[4][64];

    // softmax stats over the full T=1024 scores (each block recomputes)
    float4 s = *(const float4*)(g_scores + b * TLEN + tid * 4);
    float m = fmaxf(fmaxf(s.x, s.y), fmaxf(s.z, s.w));
#pragma unroll
    for (int off = 16; off; off >>= 1) m = fmaxf(m, __shfl_xor_sync(0xffffffffu, m, off));
    if (lane == 0) red[warp] = m;
    __syncthreads();
    if (tid == 0) {
        float mm = red[0];
#pragma unroll
        for (int i = 1; i < 8; i++) mm = fmaxf(mm, red[i]);
        red[0] = mm;
    }
    __syncthreads();
    float mx = red[0];
    __syncthreads();

    float4 e;
    e.x = __expf(s.x - mx); e.y = __expf(s.y - mx);
    e.z = __expf(s.z - mx); e.w = __expf(s.w - mx);
    float t = e.x + e.y + e.z + e.w;
#pragma unroll
    for (int off = 16; off; off >>= 1) t += __shfl_xor_sync(0xffffffffu, t, off);
    if (lane == 0) red[warp] = t;
    __syncthreads();
    if (tid == 0) {
        float ss = 0.0f;
#pragma unroll
        for (int i = 0; i < 8; i++) ss += red[i];
        red[0] = 1.0f / ss;
    }
    __syncthreads();
    float inv = red[0];

    // write normalized weights for this block's 256-chunk
    if ((tid >> 6) == ch) {
        float4 wv;
        wv.x = e.x * inv; wv.y = e.y * inv; wv.z = e.z * inv; wv.w = e.w * inv;
        ((float4*)sw)[tid & 63] = wv;
    }
    __syncthreads();

    // context partial over t in [ch*256, ch*256+256)
    int u4 = tid & 63;
    int tg = tid >> 6;
    const float* mp = memory + ((size_t)b * TLEN + ch * 256 + tg * 64) * U + u4 * 4;
    const float* wp = sw + tg * 64;
    float4 c = make_float4(0.f, 0.f, 0.f, 0.f);
#pragma unroll 8
    for (int i = 0; i < 64; i++) {
        float wv = wp[i];
        float4 m4 = *(const float4*)(mp + (size_t)i * U);
        c.x += wv * m4.x; c.y += wv * m4.y; c.z += wv * m4.z; c.w += wv * m4.w;
    }
    part[tg][u4] = c;
    __syncthreads();

    if (tg == 0) {
        float4 a = part[0][u4], b2 = part[1][u4], c2 = part[2][u4], d2 = part[3][u4];
        float4 r;
        r.x = a.x + b2.x + c2.x + d2.x;
        r.y = a.y + b2.y + c2.y + d2.y;
        r.z = a.z + b2.z + c2.z + d2.z;
        r.w = a.w + b2.w + c2.w + d2.w;
        *(float4*)(g_ctxpart + ((size_t)b * 4 + ch) * U + u4 * 4) = r;
    }
}

__global__ void k_ctx_reduce() {
    int b = blockIdx.x, j = threadIdx.x;
    g_cat[b * 2 * U + U + j] = g_ctxpart[((size_t)b * 4 + 0) * U + j]
                             + g_ctxpart[((size_t)b * 4 + 1) * U + j]
                             + g_ctxpart[((size_t)b * 4 + 2) * U + j]
                             + g_ctxpart[((size_t)b * 4 + 3) * U + j];
}

// ================= launch =================
extern "C" void kernel_launch(void* const* d_in, const int* in_sizes, int n_in,
                              void* d_out, int out_size) {
    const float* dec   = (const float*)d_in[0];
    const float* mem   = (const float*)d_in[1];
    const float* ah    = (const float*)d_in[2];
    const float* h1    = (const float*)d_in[3];
    const float* h2    = (const float*)d_in[4];
    const float* W1    = (const float*)d_in[5];
    const float* W2    = (const float*)d_in[6];
    const float* v     = (const float*)d_in[7];
    const float* aWih  = (const float*)d_in[8];
    const float* aWhh  = (const float*)d_in[9];
    const float* abih  = (const float*)d_in[10];
    const float* abhh  = (const float*)d_in[11];
    const float* g1Wih = (const float*)d_in[12];
    const float* g1Whh = (const float*)d_in[13];
    const float* g1bih = (const float*)d_in[14];
    const float* g1bhh = (const float*)d_in[15];
    const float* g2Wih = (const float*)d_in[16];
    const float* g2Whh = (const float*)d_in[17];
    const float* g2bih = (const float*)d_in[18];
    const float* g2bhh = (const float*)d_in[19];
    const float* projW = (const float*)d_in[20];
    const float* projb = (const float*)d_in[21];
    const float* outW  = (const float*)d_in[22];
    const float* outb  = (const float*)d_in[23];
    float* out = (float*)d_out;

    float* p_ghA;   cudaGetSymbolAddress((void**)&p_ghA, g_ghA);
    float* p_gh1;   cudaGetSymbolAddress((void**)&p_gh1, g_gh1);
    float* p_gh2;   cudaGetSymbolAddress((void**)&p_gh2, g_gh2);
    float* p_cat;   cudaGetSymbolAddress((void**)&p_cat, g_cat);
    float* p_x1;    cudaGetSymbolAddress((void**)&p_x1, g_x1);
    float* p_x2;    cudaGetSymbolAddress((void**)&p_x2, g_x2);
    float* p_bf;    cudaGetSymbolAddress((void**)&p_bf, g_bf);
    float* p_query; cudaGetSymbolAddress((void**)&p_query, g_query);

    static int smem_set = 0;
    const int SC_SMEM   = (2 * 128 * 36 + 2 * 32 * 264) * 4;  // 104448 B
    const int G256_SMEM = 96 * 268 * 4;                        // 102912 B
    const int G512_SMEM = 96 * 524 * 4;                        // 201216 B
    const int R128_SMEM = 128 * 140 * 4;                       // 71680 B
    const int R256_SMEM = 128 * 268 * 4;                       // 137216 B
    if (!smem_set) {
        cudaFuncSetAttribute(k_scores3, cudaFuncAttributeMaxDynamicSharedMemorySize, SC_SMEM);
        cudaFuncSetAttribute(k_gemm_1s<256>, cudaFuncAttributeMaxDynamicSharedMemorySize, G256_SMEM);
        cudaFuncSetAttribute(k_gemm_1s<512>, cudaFuncAttributeMaxDynamicSharedMemorySize, G512_SMEM);
        cudaFuncSetAttribute(k_gemm_multi_1s<256>, cudaFuncAttributeMaxDynamicSharedMemorySize, G256_SMEM);
        cudaFuncSetAttribute(k_gru_1s<128>, cudaFuncAttributeMaxDynamicSharedMemorySize, R128_SMEM);
        cudaFuncSetAttribute(k_gru_1s<256>, cudaFuncAttributeMaxDynamicSharedMemorySize, R256_SMEM);
        smem_set = 1;
    }

    k_prepW1<<<dim3(8, 8), dim3(32, 8)>>>(W1);

    // hidden-side gate pre-acts (input-independent): one multi launch, 144 blocks
    GemmJobs3 jobs;
    jobs.j[0] = { ah, aWhh,  abhh,  p_ghA, U, 768, 768 };
    jobs.j[1] = { h1, g1Whh, g1bhh, p_gh1, U, 768, 768 };
    jobs.j[2] = { h2, g2Whh, g2bhh, p_gh2, U, 768, 768 };
    k_gemm_multi_1s<256><<<dim3(12, 4, 3), 256, G256_SMEM>>>(jobs);

    // attention GRU: fused gate-GEMM + combine -> d_t
    k_gru_1s<128><<<dim3(8, 4), 256, R128_SMEM>>>(dec, INWID, aWih, abih,
                                                  p_ghA, ah, p_cat, 2 * U,
                                                  out + DT_OFF, nullptr);

    // query = d_t @ W2^T
    k_gemm_1s<256><<<dim3(4, 4), 256, G256_SMEM>>>(p_cat, 2 * U, W2, nullptr,
                                                   p_query, U, U);

    k_scores3<<<dim3(BATCH, TLEN / 128), 256, SC_SMEM>>>(mem, v);
    k_context2<<<dim3(BATCH, 4), 256>>>(mem);
    k_ctx_reduce<<<BATCH, 256>>>();

    // gru1_input = [d_t | ctx] @ projW^T + projb
    k_gemm_1s<512><<<dim3(4, 4), 256, G512_SMEM>>>(p_cat, 2 * U, projW, projb,
                                                   p_x1, U, U);

    // GRU1: fused gate-GEMM + combine -> h1 and x2 = x1 + h1
    k_gru_1s<256><<<dim3(8, 4), 256, R256_SMEM>>>(p_x1, U, g1Wih, g1bih,
                                                  p_gh1, h1, out + G1_OFF, U,
                                                  nullptr, p_x2);

    // GRU2: fused gate-GEMM + combine -> h2 and bf = x2 + h2
    k_gru_1s<256><<<dim3(8, 4), 256, R256_SMEM>>>(p_x2, U, g2Wih, g2bih,
                                                  p_gh2, h2, out + G2_OFF, U,
                                                  nullptr, p_bf);

    // output head
    k_gemm_1s<256><<<dim3(7, 4), 256, G256_SMEM>>>(p_bf, U, outW, outb,
                                                   out + OUT_OFF, OUTD, OUTD);
}

// round 15
// speedup vs baseline: 1.2630x; 1.2630x over previous
#include <cuda_runtime.h>
#include <cstdint>
#include <math.h>

#define U 256
#define INWID 128
#define BATCH 128
#define TLEN 1024
#define OUTD 400

// d_out layout: output [B*400] | d_t [B*256] | gru1_h [B*256] | gru2_h [B*256]
#define OUT_OFF 0
#define DT_OFF  (BATCH*OUTD)
#define G1_OFF  (DT_OFF + BATCH*U)
#define G2_OFF  (G1_OFF + BATCH*U)

// -------- scratch (no allocations allowed) --------
__device__ __align__(16) float g_W1tp[256 * 264];   // tf32, transposed, padded rows
__device__ __align__(16) float g_query[BATCH * U];
__device__ __align__(16) float g_scores[BATCH * TLEN];
__device__ __align__(16) float g_ghA[BATCH * 3 * U];
__device__ __align__(16) float g_gh1[BATCH * 3 * U];
__device__ __align__(16) float g_gh2[BATCH * 3 * U];
__device__ __align__(16) float g_cat[BATCH * 2 * U];   // [d_t | ctx(atomic)]
__device__ __align__(16) float g_x1[BATCH * U];
__device__ __align__(16) float g_x2[BATCH * U];
__device__ __align__(16) float g_bf[BATCH * U];

__device__ __forceinline__ float sigmoidf_(float x) {
    return 1.0f / (1.0f + __expf(-x));
}
__device__ __forceinline__ float tanh_fast(float x) {
    float y;
    asm("tanh.approx.f32 %0, %1;" : "=f"(y) : "f"(x));
    return y;
}
__device__ __forceinline__ uint32_t f32_to_tf32(float x) {
    uint32_t r;
    asm("cvt.rna.tf32.f32 %0, %1;" : "=r"(r) : "f"(x));
    return r;
}
__device__ __forceinline__ float tf32v(float x) {
    return __uint_as_float(f32_to_tf32(x));
}
__device__ __forceinline__ void mma_tf32(float c[4], const uint32_t a[4], const uint32_t b[2]) {
    asm volatile(
        "mma.sync.aligned.m16n8k8.row.col.f32.tf32.tf32.f32 "
        "{%0,%1,%2,%3}, {%4,%5,%6,%7}, {%8,%9}, {%0,%1,%2,%3};\n"
        : "+f"(c[0]), "+f"(c[1]), "+f"(c[2]), "+f"(c[3])
        : "r"(a[0]), "r"(a[1]), "r"(a[2]), "r"(a[3]), "r"(b[0]), "r"(b[1]));
}
__device__ __forceinline__ uint32_t smem_u32(const void* p) {
    uint32_t a;
    asm("{ .reg .u64 t; cvta.to.shared.u64 t, %1; cvt.u32.u64 %0, t; }" : "=r"(a) : "l"(p));
    return a;
}
__device__ __forceinline__ void cp_async16(uint32_t dst, const void* src) {
    asm volatile("cp.async.ca.shared.global [%0], [%1], 16;\n" :: "r"(dst), "l"(src));
}
__device__ __forceinline__ void cp_async16_p(uint32_t dst, const void* src, bool pred) {
    int sz = pred ? 16 : 0;
    asm volatile("cp.async.ca.shared.global [%0], [%1], 16, %2;\n"
                 :: "r"(dst), "l"(src), "r"(sz));
}
__device__ __forceinline__ void cp_commit() {
    asm volatile("cp.async.commit_group;\n");
}
__device__ __forceinline__ void cp_wait1() {
    asm volatile("cp.async.wait_group 1;\n" ::: "memory");
}
__device__ __forceinline__ void cp_wait0() {
    asm volatile("cp.async.wait_group 0;\n" ::: "memory");
}

// ================= prep: W1 [j][k] -> W1tp [k][j] (tf32, 264-stride) ========
__global__ void k_prepW1(const float* __restrict__ W1) {
    __shared__ float tile[32][33];
    int k0 = blockIdx.x * 32, j0 = blockIdx.y * 32;
    int tx = threadIdx.x, ty = threadIdx.y;  // 32 x 8
#pragma unroll
    for (int r = 0; r < 32; r += 8)
        tile[ty + r][tx] = W1[(j0 + ty + r) * U + k0 + tx];
    __syncthreads();
#pragma unroll
    for (int r = 0; r < 32; r += 8)
        g_W1tp[(size_t)(k0 + ty + r) * 264 + j0 + tx] = tf32v(tile[tx][ty + r]);
}

// ================= K2: scores via pipelined tf32 mma (proven, unchanged) ====
__global__ void __launch_bounds__(256, 1)
k_scores3(const float* __restrict__ memory, const float* __restrict__ v) {
    extern __shared__ float dsm[];
    float* Abuf = dsm;                         // 2 * 4608 floats
    float* Bbuf = dsm + 2 * 128 * 36;          // 2 * 8448 floats
    __shared__ float sq[U], sv[U];
    __shared__ float spart[128][4];

    int b = blockIdx.x, t0 = blockIdx.y * 128;
    int tid = threadIdx.x, lane = tid & 31, w = tid >> 5;

    sq[tid] = g_query[b * U + tid];
    sv[tid] = v[tid];

    const float* Abase = memory + ((size_t)b * TLEN + t0) * U;

    int mbase = (w & 1) * 64;
    int nbase = (w >> 1) * 64;
    int r0 = lane >> 2, cA = lane & 3;
    int rB = lane & 3, cB = lane >> 2;

    float acc[4][8][4];
#pragma unroll
    for (int mt = 0; mt < 4; mt++)
#pragma unroll
        for (int nt = 0; nt < 8; nt++)
#pragma unroll
            for (int i = 0; i < 4; i++) acc[mt][nt][i] = 0.0f;

#pragma unroll
    for (int i = 0; i < 4; i++) {
        int u = tid + 256 * i;
        int row = u >> 3, c4 = (u & 7) * 4;
        cp_async16(smem_u32(Abuf + row * 36 + c4), Abase + (size_t)row * U + c4);
    }
#pragma unroll
    for (int i = 0; i < 8; i++) {
        int u = tid + 256 * i;
        int row = u >> 6, c4 = (u & 63) * 4;
        cp_async16(smem_u32(Bbuf + row * 264 + c4), g_W1tp + (size_t)row * 264 + c4);
    }
    cp_commit();

    for (int kc = 0; kc < 8; kc++) {
        int buf = kc & 1;
        if (kc < 7) {
            float* An = Abuf + (buf ^ 1) * 4608;
            float* Bn = Bbuf + (buf ^ 1) * 8448;
#pragma unroll
            for (int i = 0; i < 4; i++) {
                int u = tid + 256 * i;
                int row = u >> 3, c4 = (u & 7) * 4;
                cp_async16(smem_u32(An + row * 36 + c4),
                           Abase + (size_t)row * U + (kc + 1) * 32 + c4);
            }
#pragma unroll
            for (int i = 0; i < 8; i++) {
                int u = tid + 256 * i;
                int row = u >> 6, c4 = (u & 63) * 4;
                cp_async16(smem_u32(Bn + row * 264 + c4),
                           g_W1tp + (size_t)((kc + 1) * 32 + row) * 264 + c4);
            }
            cp_commit();
            cp_wait1();
        } else {
            cp_wait0();
        }
        __syncthreads();

        const float* Ac = Abuf + buf * 4608;
        const float* Bc = Bbuf + buf * 8448;
#pragma unroll
        for (int kk = 0; kk < 32; kk += 8) {
            uint32_t a[4][4];
#pragma unroll
            for (int mt = 0; mt < 4; mt++) {
                a[mt][0] = f32_to_tf32(Ac[(mbase + mt * 16 + r0) * 36 + kk + cA]);
                a[mt][1] = f32_to_tf32(Ac[(mbase + mt * 16 + r0 + 8) * 36 + kk + cA]);
                a[mt][2] = f32_to_tf32(Ac[(mbase + mt * 16 + r0) * 36 + kk + cA + 4]);
                a[mt][3] = f32_to_tf32(Ac[(mbase + mt * 16 + r0 + 8) * 36 + kk + cA + 4]);
            }
            uint32_t bb[8][2];
#pragma unroll
            for (int nt = 0; nt < 8; nt++) {
                int j = nbase + nt * 8 + cB;
                bb[nt][0] = __float_as_uint(Bc[(kk + rB) * 264 + j]);
                bb[nt][1] = __float_as_uint(Bc[(kk + rB + 4) * 264 + j]);
            }
#pragma unroll
            for (int mt = 0; mt < 4; mt++)
#pragma unroll
                for (int nt = 0; nt < 8; nt++)
                    mma_tf32(acc[mt][nt], a[mt], bb[nt]);
        }
        __syncthreads();
    }

    float part[8];
#pragma unroll
    for (int i = 0; i < 8; i++) part[i] = 0.0f;
    int q4 = lane & 3;
#pragma unroll
    for (int mt = 0; mt < 4; mt++) {
#pragma unroll
        for (int nt = 0; nt < 8; nt++) {
            int j0 = nbase + nt * 8 + 2 * q4;
            float q0 = sq[j0], q1 = sq[j0 + 1];
            float v0 = sv[j0], v1 = sv[j0 + 1];
            part[mt * 2 + 0] += v0 * tanh_fast(acc[mt][nt][0] + q0) + v1 * tanh_fast(acc[mt][nt][1] + q1);
            part[mt * 2 + 1] += v0 * tanh_fast(acc[mt][nt][2] + q0) + v1 * tanh_fast(acc[mt][nt][3] + q1);
        }
    }
#pragma unroll
    for (int i = 0; i < 8; i++) {
        part[i] += __shfl_xor_sync(0xffffffffu, part[i], 1);
        part[i] += __shfl_xor_sync(0xffffffffu, part[i], 2);
    }
    if ((lane & 3) == 0) {
#pragma unroll
        for (int mt = 0; mt < 4; mt++) {
            spart[mbase + mt * 16 + r0][w >> 1] = part[mt * 2 + 0];
            spart[mbase + mt * 16 + r0 + 8][w >> 1] = part[mt * 2 + 1];
        }
    }
    __syncthreads();
    if (tid < 128) {
        float s = spart[tid][0] + spart[tid][1] + spart[tid][2] + spart[tid][3];
        g_scores[b * TLEN + t0 + tid] = s;
    }
}

// ====== Pipelined GEMM, 64-wide K chunks: C[128 x 64tile] = A @ W^T + bias ==
#define SK64 68
#define AF64 (128 * SK64)
#define WF64 (64 * SK64)
template<int K>
__device__ __forceinline__ void gemm_pipe64(const float* __restrict__ A, int lda,
                                            const float* __restrict__ W,
                                            const float* __restrict__ bias,
                                            float* __restrict__ C, int ldc,
                                            int N, int n0, float* dsm) {
    constexpr int NCH = K / 64;
    float* Ab = dsm;
    float* Wb = dsm + 2 * AF64;
    int tid = threadIdx.x, lane = tid & 31, w = tid >> 5;

    float acc[2][4][4];
#pragma unroll
    for (int mt = 0; mt < 2; mt++)
#pragma unroll
        for (int nt = 0; nt < 4; nt++)
#pragma unroll
            for (int i = 0; i < 4; i++) acc[mt][nt][i] = 0.0f;

    int mbase = (w & 3) * 32;
    int nbase = (w >> 2) * 32;
    int r0 = lane >> 2, cA = lane & 3;
    int rW = lane >> 2, cW = lane & 3;

    // prologue: A 128x64 (2048 f4), W 64x64 (1024 f4)
#pragma unroll
    for (int i = 0; i < 8; i++) {
        int u = tid + 256 * i;
        int row = u >> 4, c4 = (u & 15) * 4;
        cp_async16(smem_u32(Ab + row * SK64 + c4), A + (size_t)row * lda + c4);
    }
#pragma unroll
    for (int i = 0; i < 4; i++) {
        int u = tid + 256 * i;
        int row = u >> 4, c4 = (u & 15) * 4;
        int n = n0 + row;
        cp_async16_p(smem_u32(Wb + row * SK64 + c4),
                     W + (size_t)(n < N ? n : N - 1) * K + c4, n < N);
    }
    cp_commit();

#pragma unroll
    for (int kc = 0; kc < NCH; kc++) {
        int buf = kc & 1;
        if (kc + 1 < NCH) {
            float* An = Ab + (buf ^ 1) * AF64;
            float* Wn = Wb + (buf ^ 1) * WF64;
            int k0 = (kc + 1) * 64;
#pragma unroll
            for (int i = 0; i < 8; i++) {
                int u = tid + 256 * i;
                int row = u >> 4, c4 = (u & 15) * 4;
                cp_async16(smem_u32(An + row * SK64 + c4), A + (size_t)row * lda + k0 + c4);
            }
#pragma unroll
            for (int i = 0; i < 4; i++) {
                int u = tid + 256 * i;
                int row = u >> 4, c4 = (u & 15) * 4;
                int n = n0 + row;
                cp_async16_p(smem_u32(Wn + row * SK64 + c4),
                             W + (size_t)(n < N ? n : N - 1) * K + k0 + c4, n < N);
            }
            cp_commit();
            cp_wait1();
        } else {
            cp_wait0();
        }
        __syncthreads();

        const float* Ac = Ab + buf * AF64;
        const float* Wc = Wb + buf * WF64;
#pragma unroll
        for (int kk = 0; kk < 64; kk += 8) {
            uint32_t a[2][4];
#pragma unroll
            for (int mt = 0; mt < 2; mt++) {
                a[mt][0] = f32_to_tf32(Ac[(mbase + mt * 16 + r0) * SK64 + kk + cA]);
                a[mt][1] = f32_to_tf32(Ac[(mbase + mt * 16 + r0 + 8) * SK64 + kk + cA]);
                a[mt][2] = f32_to_tf32(Ac[(mbase + mt * 16 + r0) * SK64 + kk + cA + 4]);
                a[mt][3] = f32_to_tf32(Ac[(mbase + mt * 16 + r0 + 8) * SK64 + kk + cA + 4]);
            }
            uint32_t bb[4][2];
#pragma unroll
            for (int nt = 0; nt < 4; nt++) {
                int nl = nbase + nt * 8 + rW;
                bb[nt][0] = f32_to_tf32(Wc[nl * SK64 + kk + cW]);
                bb[nt][1] = f32_to_tf32(Wc[nl * SK64 + kk + cW + 4]);
            }
#pragma unroll
            for (int mt = 0; mt < 2; mt++)
#pragma unroll
                for (int nt = 0; nt < 4; nt++)
                    mma_tf32(acc[mt][nt], a[mt], bb[nt]);
        }
        __syncthreads();
    }

    int q4 = lane & 3;
#pragma unroll
    for (int mt = 0; mt < 2; mt++) {
#pragma unroll
        for (int nt = 0; nt < 4; nt++) {
            int m = mbase + mt * 16 + r0;
            int n = n0 + nbase + nt * 8 + 2 * q4;
            if (n < N) {
                float b0 = bias ? bias[n] : 0.0f;
                float b1 = bias ? bias[n + 1] : 0.0f;
                C[(size_t)m * ldc + n]           = acc[mt][nt][0] + b0;
                C[(size_t)m * ldc + n + 1]       = acc[mt][nt][1] + b1;
                C[(size_t)(m + 8) * ldc + n]     = acc[mt][nt][2] + b0;
                C[(size_t)(m + 8) * ldc + n + 1] = acc[mt][nt][3] + b1;
            }
        }
    }
}

template<int K>
__global__ void __launch_bounds__(256)
k_gemm_p64(const float* __restrict__ A, int lda, const float* __restrict__ W,
           const float* __restrict__ bias, float* __restrict__ C, int ldc, int N) {
    extern __shared__ float dsm[];
    gemm_pipe64<K>(A, lda, W, bias, C, ldc, N, blockIdx.x * 64, dsm);
}

struct GemmJob {
    const float* A; const float* W; const float* bias; float* C;
    int lda; int ldc; int N;
};
struct GemmJobs3 { GemmJob j[3]; };

__global__ void __launch_bounds__(256)
k_gemm_multi64(GemmJobs3 jobs) {
    extern __shared__ float dsm[];
    GemmJob jb = jobs.j[blockIdx.y];
    gemm_pipe64<256>(jb.A, jb.lda, jb.W, jb.bias, jb.C, jb.ldc, jb.N,
                     blockIdx.x * 64, dsm);
}

// ========== Fused gate-GEMM + GRU combine, 64-wide K chunks ================
#define GRA64 (32 * SK64)    // A buffer
#define GRW64 (192 * SK64)   // W buffer
template<int K>
__global__ void __launch_bounds__(256)
k_gru64(const float* __restrict__ A, int lda,
        const float* __restrict__ Wih, const float* __restrict__ bih,
        const float* __restrict__ gh, const float* __restrict__ h0,
        float* __restrict__ hA, int sHA, float* __restrict__ hB,
        float* __restrict__ xout, float* __restrict__ zctx) {
    extern __shared__ float dsm[];
    constexpr int NCH = K / 64;
    float* Ab = dsm;
    float* Wb = dsm + 2 * GRA64;
    int tid = threadIdx.x, lane = tid & 31, w = tid >> 5;
    int n0 = blockIdx.x * 64;
    int m0 = blockIdx.y * 32;
    int mbase = (w & 1) * 16, nbase = (w >> 1) * 16;
    int r0 = lane >> 2, cA = lane & 3;
    int rW = lane >> 2, cW = lane & 3;

    float acc[3][2][4];
#pragma unroll
    for (int g = 0; g < 3; g++)
#pragma unroll
        for (int nt = 0; nt < 2; nt++)
#pragma unroll
            for (int i = 0; i < 4; i++) acc[g][nt][i] = 0.0f;

    // prologue: A 32x64 (512 f4), W 192x64 (3072 f4)
#pragma unroll
    for (int i = 0; i < 2; i++) {
        int u = tid + 256 * i;
        int row = u >> 4, c4 = (u & 15) * 4;
        cp_async16(smem_u32(Ab + row * SK64 + c4), A + (size_t)(m0 + row) * lda + c4);
    }
#pragma unroll
    for (int i = 0; i < 12; i++) {
        int u = tid + 256 * i;
        int row = u >> 4, c4 = (u & 15) * 4;
        int wr = (row >> 6) * 256 + n0 + (row & 63);
        cp_async16(smem_u32(Wb + row * SK64 + c4), Wih + (size_t)wr * K + c4);
    }
    cp_commit();

    // zero the ctx half of g_cat for this block's rows (attention call only)
    if (zctx && n0 == 0) {
#pragma unroll
        for (int i = 0; i < 8; i++) {
            int u = tid + 256 * i;
            int row = u >> 6, c4 = (u & 63) * 4;
            *(float4*)(zctx + (size_t)(m0 + row) * 512 + 256 + c4) =
                make_float4(0.f, 0.f, 0.f, 0.f);
        }
    }

#pragma unroll
    for (int kc = 0; kc < NCH; kc++) {
        int buf = kc & 1;
        if (kc + 1 < NCH) {
            float* An = Ab + (buf ^ 1) * GRA64;
            float* Wn = Wb + (buf ^ 1) * GRW64;
            int k0 = (kc + 1) * 64;
#pragma unroll
            for (int i = 0; i < 2; i++) {
                int u = tid + 256 * i;
                int row = u >> 4, c4 = (u & 15) * 4;
                cp_async16(smem_u32(An + row * SK64 + c4),
                           A + (size_t)(m0 + row) * lda + k0 + c4);
            }
#pragma unroll
            for (int i = 0; i < 12; i++) {
                int u = tid + 256 * i;
                int row = u >> 4, c4 = (u & 15) * 4;
                int wr = (row >> 6) * 256 + n0 + (row & 63);
                cp_async16(smem_u32(Wn + row * SK64 + c4), Wih + (size_t)wr * K + k0 + c4);
            }
            cp_commit();
            cp_wait1();
        } else {
            cp_wait0();
        }
        __syncthreads();

        const float* Ac = Ab + buf * GRA64;
        const float* Wc = Wb + buf * GRW64;
#pragma unroll
        for (int kk = 0; kk < 64; kk += 8) {
            uint32_t a[4];
            a[0] = f32_to_tf32(Ac[(mbase + r0) * SK64 + kk + cA]);
            a[1] = f32_to_tf32(Ac[(mbase + r0 + 8) * SK64 + kk + cA]);
            a[2] = f32_to_tf32(Ac[(mbase + r0) * SK64 + kk + cA + 4]);
            a[3] = f32_to_tf32(Ac[(mbase + r0 + 8) * SK64 + kk + cA + 4]);
#pragma unroll
            for (int g = 0; g < 3; g++) {
#pragma unroll
                for (int nt = 0; nt < 2; nt++) {
                    uint32_t bb[2];
                    int nl = g * 64 + nbase + nt * 8 + rW;
                    bb[0] = f32_to_tf32(Wc[nl * SK64 + kk + cW]);
                    bb[1] = f32_to_tf32(Wc[nl * SK64 + kk + cW + 4]);
                    mma_tf32(acc[g][nt], a, bb);
                }
            }
        }
        __syncthreads();
    }

    // epilogue: GRU combine
    int q4 = lane & 3;
#pragma unroll
    for (int nt = 0; nt < 2; nt++) {
#pragma unroll
        for (int half = 0; half < 2; half++) {
            int m = m0 + mbase + r0 + half * 8;
#pragma unroll
            for (int c = 0; c < 2; c++) {
                int nn = n0 + nbase + nt * 8 + 2 * q4 + c;
                int ai = half * 2 + c;
                float gir = acc[0][nt][ai] + bih[nn];
                float giz = acc[1][nt][ai] + bih[256 + nn];
                float gin = acc[2][nt][ai] + bih[512 + nn];
                float ghr = gh[m * 768 + nn];
                float ghz = gh[m * 768 + 256 + nn];
                float ghn = gh[m * 768 + 512 + nn];
                float r = sigmoidf_(gir + ghr);
                float z = sigmoidf_(giz + ghz);
                float nv = tanhf(gin + r * ghn);
                float h = (1.0f - z) * nv + z * h0[m * 256 + nn];
                hA[(size_t)m * sHA + nn] = h;
                if (hB) hB[m * 256 + nn] = h;
                if (xout) xout[m * 256 + nn] = A[(size_t)m * lda + nn] + h;
            }
        }
    }
}

// ====== context with fused softmax stats; atomic ctx into g_cat ============
__global__ void __launch_bounds__(256, 4)
k_context2(const float* __restrict__ memory) {
    int b = blockIdx.x, ch = blockIdx.y;
    int tid = threadIdx.x;
    int lane = tid & 31, warp = tid >> 5;

    __shared__ float red[8];
    __shared__ float sw[256];
    __shared__ float4 part[4][64];

    // softmax stats over the full T=1024 scores (each block recomputes)
    float4 s = *(const float4*)(g_scores + b * TLEN + tid * 4);
    float m = fmaxf(fmaxf(s.x, s.y), fmaxf(s.z, s.w));
#pragma unroll
    for (int off = 16; off; off >>= 1) m = fmaxf(m, __shfl_xor_sync(0xffffffffu, m, off));
    if (lane == 0) red[warp] = m;
    __syncthreads();
    if (tid == 0) {
        float mm = red[0];
#pragma unroll
        for (int i = 1; i < 8; i++) mm = fmaxf(mm, red[i]);
        red[0] = mm;
    }
    __syncthreads();
    float mx = red[0];
    __syncthreads();

    float4 e;
    e.x = __expf(s.x - mx); e.y = __expf(s.y - mx);
    e.z = __expf(s.z - mx); e.w = __expf(s.w - mx);
    float t = e.x + e.y + e.z + e.w;
#pragma unroll
    for (int off = 16; off; off >>= 1) t += __shfl_xor_sync(0xffffffffu, t, off);
    if (lane == 0) red[warp] = t;
    __syncthreads();
    if (tid == 0) {
        float ss = 0.0f;
#pragma unroll
        for (int i = 0; i < 8; i++) ss += red[i];
        red[0] = 1.0f / ss;
    }
    __syncthreads();
    float inv = red[0];

    // write normalized weights for this block's 256-chunk
    if ((tid >> 6) == ch) {
        float4 wv;
        wv.x = e.x * inv; wv.y = e.y * inv; wv.z = e.z * inv; wv.w = e.w * inv;
        ((float4*)sw)[tid & 63] = wv;
    }
    __syncthreads();

    // context partial over t in [ch*256, ch*256+256)
    int u4 = tid & 63;
    int tg = tid >> 6;
    const float* mp = memory + ((size_t)b * TLEN + ch * 256 + tg * 64) * U + u4 * 4;
    const float* wp = sw + tg * 64;
    float4 c = make_float4(0.f, 0.f, 0.f, 0.f);
#pragma unroll 8
    for (int i = 0; i < 64; i++) {
        float wv = wp[i];
        float4 m4 = *(const float4*)(mp + (size_t)i * U);
        c.x += wv * m4.x; c.y += wv * m4.y; c.z += wv * m4.z; c.w += wv * m4.w;
    }
    part[tg][u4] = c;
    __syncthreads();

    if (tg == 0) {
        float4 a = part[0][u4], b2 = part[1][u4], c2 = part[2][u4], d2 = part[3][u4];
        float* dst = g_cat + (size_t)b * 512 + 256 + u4 * 4;
        atomicAdd(dst + 0, a.x + b2.x + c2.x + d2.x);
        atomicAdd(dst + 1, a.y + b2.y + c2.y + d2.y);
        atomicAdd(dst + 2, a.z + b2.z + c2.z + d2.z);
        atomicAdd(dst + 3, a.w + b2.w + c2.w + d2.w);
    }
}

// ================= launch =================
extern "C" void kernel_launch(void* const* d_in, const int* in_sizes, int n_in,
                              void* d_out, int out_size) {
    const float* dec   = (const float*)d_in[0];
    const float* mem   = (const float*)d_in[1];
    const float* ah    = (const float*)d_in[2];
    const float* h1    = (const float*)d_in[3];
    const float* h2    = (const float*)d_in[4];
    const float* W1    = (const float*)d_in[5];
    const float* W2    = (const float*)d_in[6];
    const float* v     = (const float*)d_in[7];
    const float* aWih  = (const float*)d_in[8];
    const float* aWhh  = (const float*)d_in[9];
    const float* abih  = (const float*)d_in[10];
    const float* abhh  = (const float*)d_in[11];
    const float* g1Wih = (const float*)d_in[12];
    const float* g1Whh = (const float*)d_in[13];
    const float* g1bih = (const float*)d_in[14];
    const float* g1bhh = (const float*)d_in[15];
    const float* g2Wih = (const float*)d_in[16];
    const float* g2Whh = (const float*)d_in[17];
    const float* g2bih = (const float*)d_in[18];
    const float* g2bhh = (const float*)d_in[19];
    const float* projW = (const float*)d_in[20];
    const float* projb = (const float*)d_in[21];
    const float* outW  = (const float*)d_in[22];
    const float* outb  = (const float*)d_in[23];
    float* out = (float*)d_out;

    float* p_ghA;   cudaGetSymbolAddress((void**)&p_ghA, g_ghA);
    float* p_gh1;   cudaGetSymbolAddress((void**)&p_gh1, g_gh1);
    float* p_gh2;   cudaGetSymbolAddress((void**)&p_gh2, g_gh2);
    float* p_cat;   cudaGetSymbolAddress((void**)&p_cat, g_cat);
    float* p_x1;    cudaGetSymbolAddress((void**)&p_x1, g_x1);
    float* p_x2;    cudaGetSymbolAddress((void**)&p_x2, g_x2);
    float* p_bf;    cudaGetSymbolAddress((void**)&p_bf, g_bf);
    float* p_query; cudaGetSymbolAddress((void**)&p_query, g_query);

    static int smem_set = 0;
    const int SC_SMEM = (2 * 128 * 36 + 2 * 32 * 264) * 4;        // 104448 B
    const int GP_SMEM = 2 * (AF64 + WF64) * 4;                    // 104448 B
    const int GR_SMEM = 2 * (GRA64 + GRW64) * 4;                  // 121856 B
    if (!smem_set) {
        cudaFuncSetAttribute(k_scores3, cudaFuncAttributeMaxDynamicSharedMemorySize, SC_SMEM);
        cudaFuncSetAttribute(k_gemm_p64<256>, cudaFuncAttributeMaxDynamicSharedMemorySize, GP_SMEM);
        cudaFuncSetAttribute(k_gemm_p64<512>, cudaFuncAttributeMaxDynamicSharedMemorySize, GP_SMEM);
        cudaFuncSetAttribute(k_gemm_multi64, cudaFuncAttributeMaxDynamicSharedMemorySize, GP_SMEM);
        cudaFuncSetAttribute(k_gru64<128>, cudaFuncAttributeMaxDynamicSharedMemorySize, GR_SMEM);
        cudaFuncSetAttribute(k_gru64<256>, cudaFuncAttributeMaxDynamicSharedMemorySize, GR_SMEM);
        smem_set = 1;
    }

    k_prepW1<<<dim3(8, 8), dim3(32, 8)>>>(W1);

    // hidden-side gate pre-acts (input-independent): one multi launch
    GemmJobs3 jobs;
    jobs.j[0] = { ah, aWhh,  abhh,  p_ghA, U, 768, 768 };
    jobs.j[1] = { h1, g1Whh, g1bhh, p_gh1, U, 768, 768 };
    jobs.j[2] = { h2, g2Whh, g2bhh, p_gh2, U, 768, 768 };
    k_gemm_multi64<<<dim3(12, 3), 256, GP_SMEM>>>(jobs);

    // attention GRU: fused gate-GEMM + combine -> d_t (also zeroes ctx half)
    k_gru64<128><<<dim3(4, 4), 256, GR_SMEM>>>(dec, INWID, aWih, abih,
                                               p_ghA, ah, p_cat, 2 * U,
                                               out + DT_OFF, nullptr, p_cat);

    // query = d_t @ W2^T
    k_gemm_p64<256><<<4, 256, GP_SMEM>>>(p_cat, 2 * U, W2, nullptr, p_query, U, U);

    k_scores3<<<dim3(BATCH, TLEN / 128), 256, SC_SMEM>>>(mem, v);
    k_context2<<<dim3(BATCH, 4), 256>>>(mem);

    // gru1_input = [d_t | ctx] @ projW^T + projb
    k_gemm_p64<512><<<4, 256, GP_SMEM>>>(p_cat, 2 * U, projW, projb, p_x1, U, U);

    // GRU1: fused gate-GEMM + combine -> h1 and x2 = x1 + h1
    k_gru64<256><<<dim3(4, 4), 256, GR_SMEM>>>(p_x1, U, g1Wih, g1bih,
                                               p_gh1, h1, out + G1_OFF, U,
                                               nullptr, p_x2, nullptr);

    // GRU2: fused gate-GEMM + combine -> h2 and bf = x2 + h2
    k_gru64<256><<<dim3(4, 4), 256, GR_SMEM>>>(p_x2, U, g2Wih, g2bih,
                                               p_gh2, h2, out + G2_OFF, U,
                                               nullptr, p_bf, nullptr);

    // output head
    k_gemm_p64<256><<<7, 256, GP_SMEM>>>(p_bf, U, outW, outb, out + OUT_OFF, OUTD, OUTD);
}